// round 15
// baseline (speedup 1.0000x reference)
#include <cuda_runtime.h>
#include <math.h>

// Problem constants
#define BATCH 64
#define SEQ   512
#define HID   1024
#define EMB   256
#define NCHAR 128

// Geometry: 128 persistent CTAs = 4 batch-groups (tb) x 32 j-tiles (tj).
// Each CTA = TWO half-CTAs (warps 0-3 = A, 4-7 = B), each an independent
// 8-batch recurrence with its own 32-CTA barrier, ANTI-PHASE enforced by a
// cross-half handshake: gemmB(s) after arriveA(s); gemmA(s+1) after arriveB(s).
#define GRID     128
#define NTHREADS 256
#define BT       16      // batch rows per CTA (8 per half)
#define JT       32      // hidden rows per CTA

#define SH_STRIDE 20     // h tile row stride (words): [16 b][4 pad] — R6-proven
#define SP_STRIDE 34     // partial row stride (words)

#define SW_FLOATS (HID * JT)                    // 32768
#define SH_FLOATS (HID * SH_STRIDE)             // 20480 (A: cols 0-7, B: cols 8-15)
#define SP_FLOATS_H (4 * 8 * SP_STRIDE)         // 1088 per half
#define SMEM_FLOATS (SW_FLOATS + SH_FLOATS + 2 * SP_FLOATS_H)
#define SMEM_BYTES  (SMEM_FLOATS * 4)           // 221,696 B

typedef unsigned long long u64;

// packed f32x2 (sm_100+): one SASS FFMA2 = 2 FMAs
#define FMA2(d, a, b)    asm("fma.rn.f32x2 %0, %1, %2, %0;" : "+l"(d) : "l"(a), "l"(b))
#define PACK2(d, lo, hi) asm("mov.b64 %0, {%1, %2};" : "=l"(d) : "f"(lo), "f"(hi))
#define BARH(id) asm volatile("bar.sync %0, 128;" :: "r"(id) : "memory")

// Device-global scratch
__device__ float g_U[NCHAR * HID];             // U = embeddings @ W_ih^T
__device__ float g_h[2][BATCH * HID];          // ping-pong hidden state
__device__ unsigned g_count[8 * 32];           // 8 group barriers (tb x half), 128B apart
__device__ volatile unsigned g_sense[8 * 32];  // sense; ends at 0 (514 phases/launch)

// ---------------------------------------------------------------------------
// Split 32-CTA half-barrier: arrive (non-blocking) + wait. One polling lane
// per CTA-half (proven low-contention pattern).
// ---------------------------------------------------------------------------
__device__ __forceinline__ void arrive_half(int ltid, unsigned* cnt,
                                            volatile unsigned* sns,
                                            unsigned s, int bid) {
    BARH(bid);                       // all 128 half-threads' stores issued
    if (ltid == 0) {
        __threadfence();
        if (atomicAdd(cnt, 1u) == 31u) {
            *cnt = 0;
            __threadfence();
            *sns = s;
        }
    }
}
__device__ __forceinline__ void wait_half(int ltid, volatile unsigned* sns,
                                          unsigned s, int bid) {
    if (ltid == 0) {
        while (*sns != s) { }
        __threadfence();
    }
    BARH(bid);
}

// ---------------------------------------------------------------------------
// Kernel 0: U[c][j] = sum_e emb[c][e] * W_ih[j][e]
// ---------------------------------------------------------------------------
__global__ void u_kernel(const float* __restrict__ emb, const float* __restrict__ wih) {
    int gt   = blockIdx.x * blockDim.x + threadIdx.x;
    int warp = gt >> 5;
    int lane = gt & 31;
    int e0   = lane * 8;
    for (int i = 0; i < 32; i++) {
        int o = warp * 32 + i;
        int c = o >> 10;
        int j = o & 1023;
        const float4* ep = (const float4*)(emb + c * EMB + e0);
        const float4* wp = (const float4*)(wih + j * EMB + e0);
        float4 e1 = __ldg(ep),     e2 = __ldg(ep + 1);
        float4 w1 = __ldg(wp),     w2 = __ldg(wp + 1);
        float acc = e1.x*w1.x + e1.y*w1.y + e1.z*w1.z + e1.w*w1.w
                  + e2.x*w2.x + e2.y*w2.y + e2.z*w2.z + e2.w*w2.w;
        acc += __shfl_xor_sync(0xffffffffu, acc, 16);
        acc += __shfl_xor_sync(0xffffffffu, acc, 8);
        acc += __shfl_xor_sync(0xffffffffu, acc, 4);
        acc += __shfl_xor_sync(0xffffffffu, acc, 2);
        acc += __shfl_xor_sync(0xffffffffu, acc, 1);
        if (lane == 0) g_U[c * HID + j] = acc;
    }
}

// ---------------------------------------------------------------------------
// Persistent RNN scan, anti-phase dual-pipeline CTA.
// ---------------------------------------------------------------------------
__global__ void __launch_bounds__(NTHREADS, 1) rnn_kernel(
    const int*   __restrict__ tids,
    const float* __restrict__ whh,
    const float* __restrict__ h0,
    const float* __restrict__ wproj,
    const float* __restrict__ bproj,
    float*       __restrict__ out)
{
    extern __shared__ float smem[];
    float* sW = smem;                         // [1024][32]  W slice, transposed
    float* sH = smem + SW_FLOATS;             // [1024][20]  h tile (A: 0-7, B: 8-15)
    __shared__ volatile int hs_step[2];       // handshake: last arrived step per half

    const int tid = threadIdx.x;
    const int cta = blockIdx.x;
    const int tb  = cta >> 5;      // 0..3
    const int tj  = cta & 31;      // 0..31
    const int b0  = tb * BT;
    const int j0  = tj * JT;

    if (tid == 0) { hs_step[0] = -1; hs_step[1] = -1; }

    // one-time: W_hh slice transposed into SMEM (whole CTA)
    for (int idx = tid; idx < JT * HID; idx += NTHREADS) {
        int jj = idx >> 10;
        int k  = idx & 1023;
        sW[k * JT + jj] = whh[(j0 + jj) * HID + k];
    }
    // one-time: init h ping buffer (this CTA's 16b x 32j tile)
    for (int idx = tid; idx < BT * JT; idx += NTHREADS) {
        int bb = idx >> 5;
        int jj = idx & 31;
        g_h[0][(b0 + bb) * HID + (j0 + jj)] = h0[j0 + jj];
    }
    __syncthreads();               // W + init + hs flags visible CTA-wide

    // ---- half-CTA decomposition ----
    const int half = tid >> 7;     // 0 = A (warps 0-3), 1 = B (warps 4-7)
    const int ltid = tid & 127;
    const int bid  = half + 1;     // named barrier id
    const int grp  = tb * 2 + half;
    const int b0g  = b0 + half * 8;
    unsigned*          cnt = &g_count[grp * 32];
    volatile unsigned* sns = &g_sense[grp * 32];
    float* sP = smem + SW_FLOATS + SH_FLOATS + half * SP_FLOATS_H;

    unsigned bs = 1;
    arrive_half(ltid, cnt, sns, bs, bid);      // phase 1 (init visible group-wide)
    wait_half(ltid, sns, bs, bid);

    const int kq = ltid >> 5;      // warp-in-half = k quarter (0..3)
    const int l  = tid & 31;
    const int jg = l & 7;          // 4 j's
    const int ks = l >> 3;         // 0..3
    const int klane = kq * 4 + ks; // 0..15

    const float* hptr0 = sH + klane * SH_STRIDE + half * 8;
    const float* wptr0 = sW + klane * JT + jg * 4;

    // staging: thread -> (bb 0..7 within half, kslot 0..15); 16 float4 each
    const int st_bb = ltid & 7;
    const int st_ks = ltid >> 3;   // 0..15

    // combine: thread -> (cjj, cbp)
    const int cjj = ltid & 31;
    const int cbp = ltid >> 5;     // 0..3
    const int cb0 = b0g + cbp * 2;

    for (int s = 0; s < SEQ; s++) {
        const int cur = s & 1;
        const int nxt = cur ^ 1;

        // prefetch epilogue operands under staging + GEMM
        const int   c0 = __ldg(&tids[cb0 * SEQ + s]);
        const int   c1 = __ldg(&tids[(cb0 + 1) * SEQ + s]);
        const float u0 = __ldg(&g_U[c0 * HID + j0 + cjj]);
        const float u1 = __ldg(&g_U[c1 * HID + j0 + cjj]);

        // ---- stage this half's 8 batches: sH[k][half*8 + bb] ----
        {
            const float* hrow = g_h[cur] + (b0g + st_bb) * HID;
            float* shb = sH + half * 8 + st_bb;
            #pragma unroll 4
            for (int it = 0; it < 16; it++) {
                int k = (it * 16 + st_ks) * 4;
                float4 v = __ldcg((const float4*)(hrow + k));
                shb[(k + 0) * SH_STRIDE] = v.x;
                shb[(k + 1) * SH_STRIDE] = v.y;
                shb[(k + 2) * SH_STRIDE] = v.z;
                shb[(k + 3) * SH_STRIDE] = v.w;
            }
        }
        BARH(bid);

        // ---- ANTI-PHASE handshake (scheduling only, no data dependence):
        // B's gemm(s) starts after A's arrive(s); A's gemm(s) after B's arrive(s-1).
        if (half == 0) { while (hs_step[1] < s - 1) { } }
        else           { while (hs_step[0] < s)     { } }

        // ---- packed f32x2 partial GEMM: 8b x 4j per lane, 64 k's ----
        u64 acc[4][4];
        #pragma unroll
        for (int bp = 0; bp < 4; bp++)
            #pragma unroll
            for (int j = 0; j < 4; j++) acc[bp][j] = 0ull;

        const float* hptr = hptr0;
        const float* wptr = wptr0;
        #pragma unroll 4
        for (int kk = 0; kk < 64; kk++) {
            float4 hA = *(const float4*)hptr;
            float4 hB = *(const float4*)(hptr + 4);
            float4 wv = *(const float4*)wptr;
            hptr += 16 * SH_STRIDE;
            wptr += 16 * JT;

            u64 hp[4], wd[4];
            PACK2(hp[0], hA.x, hA.y);  PACK2(hp[1], hA.z, hA.w);
            PACK2(hp[2], hB.x, hB.y);  PACK2(hp[3], hB.z, hB.w);
            PACK2(wd[0], wv.x, wv.x);  PACK2(wd[1], wv.y, wv.y);
            PACK2(wd[2], wv.z, wv.z);  PACK2(wd[3], wv.w, wv.w);

            #pragma unroll
            for (int bp = 0; bp < 4; bp++)
                #pragma unroll
                for (int j = 0; j < 4; j++)
                    FMA2(acc[bp][j], hp[bp], wd[j]);
        }

        // ---- intra-warp reduce over ks (lane bits 3,4), then stash partials ----
        #pragma unroll
        for (int bp = 0; bp < 4; bp++) {
            #pragma unroll
            for (int j = 0; j < 4; j++) {
                float lo = __uint_as_float((unsigned)(acc[bp][j] & 0xffffffffull));
                float hi = __uint_as_float((unsigned)(acc[bp][j] >> 32));
                lo += __shfl_xor_sync(0xffffffffu, lo, 8);
                hi += __shfl_xor_sync(0xffffffffu, hi, 8);
                lo += __shfl_xor_sync(0xffffffffu, lo, 16);
                hi += __shfl_xor_sync(0xffffffffu, hi, 16);
                if (ks == 0) {
                    *(float2*)(sP + (kq * 8 + jg) * SP_STRIDE + bp * 8 + j * 2)
                        = make_float2(lo, hi);
                }
            }
        }
        BARH(bid);

        // ---- combine 4 kq partials, add U, tanh, write next h ----
        {
            float slo = 0.f, shi = 0.f;
            #pragma unroll
            for (int q = 0; q < 4; q++) {
                float2 v = *(const float2*)(sP + (q * 8 + (cjj >> 2)) * SP_STRIDE
                                            + cbp * 8 + (cjj & 3) * 2);
                slo += v.x; shi += v.y;
            }
            float hn0 = tanhf(slo + u0);
            float hn1 = tanhf(shi + u1);
            __stcg(&g_h[nxt][cb0 * HID + j0 + cjj], hn0);
            __stcg(&g_h[nxt][(cb0 + 1) * HID + j0 + cjj], hn1);
        }

        // ---- arrive (phase s+2), publish handshake step, then wait ----
        bs ^= 1;
        arrive_half(ltid, cnt, sns, bs, bid);
        if (ltid == 0) hs_step[half] = s;
        wait_half(ltid, sns, bs, bid);
    }

    bs ^= 1;
    arrive_half(ltid, cnt, sns, bs, bid);       // phase 514 (sense -> 0)
    wait_half(ltid, sns, bs, bid);
    __syncthreads();                            // join halves

    // ---- final projection: out[b][c] = h_final[b] . W_proj[c] + b_proj[c] ----
    if (tid < 64) {
        const int bb = tid >> 2;
        const int cc = tid & 3;
        const int b  = b0 + bb;
        const int ch = tj * 4 + cc;
        const float* hp = g_h[0] + b * HID;
        const float* wp = wproj + ch * HID;
        float acc2 = 0.0f;
        #pragma unroll 4
        for (int k = 0; k < HID; k += 4) {
            float4 hv = __ldcg((const float4*)(hp + k));
            float4 wv = *(const float4*)(wp + k);
            acc2 += hv.x*wv.x + hv.y*wv.y + hv.z*wv.z + hv.w*wv.w;
        }
        out[b * NCHAR + ch] = acc2 + bproj[ch];
    }
}

// ---------------------------------------------------------------------------
// Launch: graph-capturable, no allocations, no syncs.
// Inputs: t, embeddings, W_ih, W_hh, h0, W_proj, b_proj.
// ---------------------------------------------------------------------------
extern "C" void kernel_launch(void* const* d_in, const int* in_sizes, int n_in,
                              void* d_out, int out_size)
{
    const int*   t     = (const int*)  d_in[0];
    const float* emb   = (const float*)d_in[1];
    const float* wih   = (const float*)d_in[2];
    const float* whh   = (const float*)d_in[3];
    const float* h0    = (const float*)d_in[4];
    const float* wproj = (const float*)d_in[5];
    const float* bproj = (const float*)d_in[6];
    float*       out   = (float*)d_out;

    cudaFuncSetAttribute(rnn_kernel, cudaFuncAttributeMaxDynamicSharedMemorySize, SMEM_BYTES);

    u_kernel<<<512, 256>>>(emb, wih);
    rnn_kernel<<<GRID, NTHREADS, SMEM_BYTES>>>(t, whh, h0, wproj, bproj, out);
}

// round 16
// speedup vs baseline: 1.2065x; 1.2065x over previous
#include <cuda_runtime.h>
#include <math.h>

// Problem constants
#define BATCH 64
#define SEQ   512
#define HID   1024
#define EMB   256
#define NCHAR 128

// Geometry (R6 winner): 128 persistent CTAs = 4 batch-groups (tb) x 32 j-tiles (tj).
// 256 threads = 8 warps. Sync = distributed single-writer producer flags.
#define GRID     128
#define NTHREADS 256
#define BT       16      // batch rows per CTA
#define JT       32      // hidden rows per CTA

#define SH_STRIDE 20     // padded h-tile row stride (words)
#define SP_STRIDE 34     // partial row stride (words)

#define SW_FLOATS (HID * JT)                    // 32768
#define SH_FLOATS (HID * SH_STRIDE)             // 20480
#define SP_FLOATS (4 * 16 * SP_STRIDE)          // 2176
#define SMEM_FLOATS (SW_FLOATS + SH_FLOATS + SP_FLOATS)
#define SMEM_BYTES  (SMEM_FLOATS * 4)           // 221,696 B

typedef unsigned long long u64;

// packed f32x2 (sm_100+): one SASS FFMA2 = 2 FMAs
#define FMA2(d, a, b)    asm("fma.rn.f32x2 %0, %1, %2, %0;" : "+l"(d) : "l"(a), "l"(b))
#define PACK2(d, lo, hi) asm("mov.b64 %0, {%1, %2};" : "=l"(d) : "f"(lo), "f"(hi))

// Device-global scratch
__device__ float g_U[NCHAR * HID];            // U = embeddings @ W_ih^T
__device__ float g_h[2][BATCH * HID];         // ping-pong hidden state
__device__ unsigned g_pflag[4][32][32];       // [tb][producer tj][pad]: flag on own 128B line
__device__ unsigned g_epoch[GRID];            // per-CTA launch epoch (monotonic tags)

// ---------------------------------------------------------------------------
// Kernel 0: U[c][j] = sum_e emb[c][e] * W_ih[j][e]
// ---------------------------------------------------------------------------
__global__ void u_kernel(const float* __restrict__ emb, const float* __restrict__ wih) {
    int gt   = blockIdx.x * blockDim.x + threadIdx.x;
    int warp = gt >> 5;
    int lane = gt & 31;
    int e0   = lane * 8;
    for (int i = 0; i < 32; i++) {
        int o = warp * 32 + i;
        int c = o >> 10;
        int j = o & 1023;
        const float4* ep = (const float4*)(emb + c * EMB + e0);
        const float4* wp = (const float4*)(wih + j * EMB + e0);
        float4 e1 = __ldg(ep),     e2 = __ldg(ep + 1);
        float4 w1 = __ldg(wp),     w2 = __ldg(wp + 1);
        float acc = e1.x*w1.x + e1.y*w1.y + e1.z*w1.z + e1.w*w1.w
                  + e2.x*w2.x + e2.y*w2.y + e2.z*w2.z + e2.w*w2.w;
        acc += __shfl_xor_sync(0xffffffffu, acc, 16);
        acc += __shfl_xor_sync(0xffffffffu, acc, 8);
        acc += __shfl_xor_sync(0xffffffffu, acc, 4);
        acc += __shfl_xor_sync(0xffffffffu, acc, 2);
        acc += __shfl_xor_sync(0xffffffffu, acc, 1);
        if (lane == 0) g_U[c * HID + j] = acc;
    }
}

// ---------------------------------------------------------------------------
// Persistent RNN scan — R6's proven compute, with the centralized barrier
// replaced by per-producer flags + per-warp pipelined slice staging.
//
// Per step s: warp w waits for producers 4w..4w+3 to publish flag >= tag(s),
// stages those 4 k-slices of h (overlapping other warps' waits), syncthreads,
// then the R6 GEMM/reduce/stash/combine, syncthreads, publish flag tag(s+1).
// Flag(s+1) also releases readers of the buffer this CTA writes at step s+1
// (write follows read in every CTA's program order) -> skew bounded, no WAR.
// ---------------------------------------------------------------------------
__global__ void __launch_bounds__(NTHREADS, 1) rnn_kernel(
    const int*   __restrict__ tids,
    const float* __restrict__ whh,
    const float* __restrict__ h0,
    const float* __restrict__ wproj,
    const float* __restrict__ bproj,
    float*       __restrict__ out)
{
    extern __shared__ float smem[];
    float* sW = smem;                         // [1024][32]   W slice, transposed
    float* sH = smem + SW_FLOATS;             // [1024][20]   h tile, transposed, padded
    float* sP = smem + SW_FLOATS + SH_FLOATS; // [4][16][34]  cross-warp partials

    const int tid = threadIdx.x;
    const int cta = blockIdx.x;
    const int tb  = cta >> 5;      // 0..3 (flag group)
    const int tj  = cta & 31;      // 0..31
    const int b0  = tb * BT;
    const int j0  = tj * JT;

    // per-launch monotonic tag base (graph replays see strictly larger tags)
    __shared__ unsigned s_tagbase;
    if (tid == 0) {
        unsigned e = g_epoch[cta] + 1u;
        g_epoch[cta] = e;
        s_tagbase = e * 1024u;
    }

    // one-time: W_hh slice transposed into SMEM
    for (int idx = tid; idx < JT * HID; idx += NTHREADS) {
        int jj = idx >> 10;
        int k  = idx & 1023;
        sW[k * JT + jj] = whh[(j0 + jj) * HID + k];
    }
    // one-time: init h ping buffer (this CTA's tile)
    for (int idx = tid; idx < BT * JT; idx += NTHREADS) {
        int bb = idx >> 5;
        int jj = idx & 31;
        g_h[0][(b0 + bb) * HID + (j0 + jj)] = h0[j0 + jj];
    }
    __syncthreads();
    const unsigned tagbase = s_tagbase;
    if (tid == 0) {                 // publish h(0) ready
        __threadfence();
        asm volatile("st.relaxed.gpu.global.u32 [%0], %1;"
                     :: "l"(&g_pflag[tb][tj][0]), "r"(tagbase) : "memory");
    }

    const int w = tid >> 5;
    const int l = tid & 31;

    // GEMM lane mapping (R6): bhalf = w&1, kq = w>>1; jg = l&7, ks = l>>3
    const int bhalf = w & 1;
    const int kq    = w >> 1;
    const int jg    = l & 7;
    const int ks    = l >> 3;
    const int klane = kq * 4 + ks;

    // staging lane mapping: lane -> (bb 0..15, ki 0..1); warp w owns slices 4w..4w+3
    const int st_bb = l & 15;
    const int st_ki = l >> 4;
    const int pbase = w * 4;

    // combine mapping (R6)
    const int jc  = tid & 31;
    const int bpg = tid >> 5;
    const int cbh = bpg >> 2;
    const int cbp = bpg & 3;
    const int cg  = cbh * 8 + (jc >> 2);
    const int cbase = cbp * 8 + (jc & 3) * 2;
    const int cb0 = b0 + cbh * 8 + cbp * 2;

    const float* hptr0 = sH + klane * SH_STRIDE + bhalf * 8;
    const float* wptr0 = sW + klane * JT + jg * 4;

    for (int s = 0; s < SEQ; s++) {
        const int cur = s & 1;
        const int nxt = cur ^ 1;
        const unsigned tag = tagbase + (unsigned)s;

        // ---- wait for THIS warp's 4 producers (h(s) slices), then stage them ----
        {
            unsigned v = tag;
            const int p = pbase + l;           // lanes 0..3 poll; others satisfied
            do {
                if (l < 4)
                    asm volatile("ld.relaxed.gpu.global.u32 %0, [%1];"
                                 : "=r"(v) : "l"(&g_pflag[tb][p][0]) : "memory");
            } while (!__all_sync(0xffffffffu, (int)(v - tag) >= 0));
            __threadfence();                   // acquire: flag seen -> h loads valid

            #pragma unroll
            for (int i = 0; i < 4; i++) {
                const int k0 = (pbase + i) * 32;
                const float* hrow = g_h[cur] + (b0 + st_bb) * HID + k0 + st_ki * 4;
                float* shb = sH + st_bb;
                #pragma unroll
                for (int m = 0; m < 4; m++) {
                    int k = k0 + st_ki * 4 + m * 8;
                    float4 v4 = __ldcg((const float4*)(hrow + m * 8));
                    shb[(k + 0) * SH_STRIDE] = v4.x;
                    shb[(k + 1) * SH_STRIDE] = v4.y;
                    shb[(k + 2) * SH_STRIDE] = v4.z;
                    shb[(k + 3) * SH_STRIDE] = v4.w;
                }
            }
        }
        __syncthreads();

        // ---- packed f32x2 partial GEMM: 8b x 4j per lane, 64 k's (R6) ----
        u64 acc[4][4];
        #pragma unroll
        for (int bp = 0; bp < 4; bp++)
            #pragma unroll
            for (int j = 0; j < 4; j++) acc[bp][j] = 0ull;

        const float* hptr = hptr0;
        const float* wptr = wptr0;
        #pragma unroll 4
        for (int kk = 0; kk < 64; kk++) {
            float4 hA = *(const float4*)hptr;
            float4 hB = *(const float4*)(hptr + 4);
            float4 wv = *(const float4*)wptr;
            hptr += 16 * SH_STRIDE;
            wptr += 16 * JT;

            u64 hp[4], wd[4];
            PACK2(hp[0], hA.x, hA.y);  PACK2(hp[1], hA.z, hA.w);
            PACK2(hp[2], hB.x, hB.y);  PACK2(hp[3], hB.z, hB.w);
            PACK2(wd[0], wv.x, wv.x);  PACK2(wd[1], wv.y, wv.y);
            PACK2(wd[2], wv.z, wv.z);  PACK2(wd[3], wv.w, wv.w);

            #pragma unroll
            for (int bp = 0; bp < 4; bp++)
                #pragma unroll
                for (int j = 0; j < 4; j++)
                    FMA2(acc[bp][j], hp[bp], wd[j]);
        }

        // ---- intra-warp reduce over ks (lane bits 3,4), then stash partials ----
        #pragma unroll
        for (int bp = 0; bp < 4; bp++) {
            #pragma unroll
            for (int j = 0; j < 4; j++) {
                float lo = __uint_as_float((unsigned)(acc[bp][j] & 0xffffffffull));
                float hi = __uint_as_float((unsigned)(acc[bp][j] >> 32));
                lo += __shfl_xor_sync(0xffffffffu, lo, 8);
                hi += __shfl_xor_sync(0xffffffffu, hi, 8);
                lo += __shfl_xor_sync(0xffffffffu, lo, 16);
                hi += __shfl_xor_sync(0xffffffffu, hi, 16);
                if (ks == 0) {
                    int g = bhalf * 8 + jg;
                    *(float2*)(sP + (kq * 16 + g) * SP_STRIDE + bp * 8 + j * 2)
                        = make_float2(lo, hi);
                }
            }
        }
        __syncthreads();

        // ---- combine 4 kq partials, add U, tanh, write next h (R6) ----
        {
            float slo = 0.f, shi = 0.f;
            #pragma unroll
            for (int q = 0; q < 4; q++) {
                float2 v = *(const float2*)(sP + (q * 16 + cg) * SP_STRIDE + cbase);
                slo += v.x; shi += v.y;
            }
            const int c0 = __ldg(&tids[cb0 * SEQ + s]);
            const int c1 = __ldg(&tids[(cb0 + 1) * SEQ + s]);
            float hn0 = tanhf(slo + __ldg(&g_U[c0 * HID + j0 + jc]));
            float hn1 = tanhf(shi + __ldg(&g_U[c1 * HID + j0 + jc]));
            __stcg(&g_h[nxt][cb0 * HID + j0 + jc], hn0);
            __stcg(&g_h[nxt][(cb0 + 1) * HID + j0 + jc], hn1);
        }
        __syncthreads();            // all h stores issued before flag

        if (tid == 0) {             // publish h(s+1) ready (also read-release)
            __threadfence();
            asm volatile("st.relaxed.gpu.global.u32 [%0], %1;"
                         :: "l"(&g_pflag[tb][tj][0]), "r"(tag + 1u) : "memory");
        }
    }

    // ---- wait for final h (all 32 producers at tag SEQ), then project ----
    {
        const unsigned tag = tagbase + (unsigned)SEQ;
        unsigned v = tag;
        const int p = pbase + l;
        do {
            if (l < 4)
                asm volatile("ld.relaxed.gpu.global.u32 %0, [%1];"
                             : "=r"(v) : "l"(&g_pflag[tb][p][0]) : "memory");
        } while (!__all_sync(0xffffffffu, (int)(v - tag) >= 0));
        __threadfence();
    }
    __syncthreads();

    // ---- final projection: out[b][c] = h_final[b] . W_proj[c] + b_proj[c] ----
    if (tid < 64) {
        const int bb = tid >> 2;
        const int cc = tid & 3;
        const int b  = b0 + bb;
        const int ch = tj * 4 + cc;
        const float* hp = g_h[0] + b * HID;
        const float* wp = wproj + ch * HID;
        float acc2 = 0.0f;
        #pragma unroll 4
        for (int k = 0; k < HID; k += 4) {
            float4 hv = __ldcg((const float4*)(hp + k));
            float4 wv = *(const float4*)(wp + k);
            acc2 += hv.x*wv.x + hv.y*wv.y + hv.z*wv.z + hv.w*wv.w;
        }
        out[b * NCHAR + ch] = acc2 + bproj[ch];
    }
}

// ---------------------------------------------------------------------------
// Launch: graph-capturable, no allocations, no syncs.
// Inputs: t, embeddings, W_ih, W_hh, h0, W_proj, b_proj.
// ---------------------------------------------------------------------------
extern "C" void kernel_launch(void* const* d_in, const int* in_sizes, int n_in,
                              void* d_out, int out_size)
{
    const int*   t     = (const int*)  d_in[0];
    const float* emb   = (const float*)d_in[1];
    const float* wih   = (const float*)d_in[2];
    const float* whh   = (const float*)d_in[3];
    const float* h0    = (const float*)d_in[4];
    const float* wproj = (const float*)d_in[5];
    const float* bproj = (const float*)d_in[6];
    float*       out   = (float*)d_out;

    cudaFuncSetAttribute(rnn_kernel, cudaFuncAttributeMaxDynamicSharedMemorySize, SMEM_BYTES);

    u_kernel<<<512, 256>>>(emb, wih);
    rnn_kernel<<<GRID, NTHREADS, SMEM_BYTES>>>(t, whh, h0, wproj, bproj, out);
}

// round 17
// speedup vs baseline: 1.2207x; 1.0117x over previous
#include <cuda_runtime.h>
#include <math.h>

// Problem constants
#define BATCH 64
#define SEQ   512
#define HID   1024
#define EMB   256
#define NCHAR 128

// Geometry: 128 persistent CTAs = 4 batch-groups (tb) x 32 j-tiles (tj).
// 256 threads = 8 warps. Sync = single-writer producer flags + PAIR-LOCAL
// named barriers: warp pair kq consumes exactly the k-block it stages.
#define GRID     128
#define NTHREADS 256
#define BT       16      // batch rows per CTA
#define JT       32      // hidden rows per CTA

#define SH_STRIDE 20     // padded h-tile row stride (words)
#define SP_STRIDE 34     // partial row stride (words)

#define SW_FLOATS (HID * JT)                    // 32768
#define SH_FLOATS (HID * SH_STRIDE)             // 20480
#define SP_FLOATS (4 * 16 * SP_STRIDE)          // 2176
#define SMEM_FLOATS (SW_FLOATS + SH_FLOATS + SP_FLOATS)
#define SMEM_BYTES  (SMEM_FLOATS * 4)           // 221,696 B

typedef unsigned long long u64;

// packed f32x2 (sm_100+): one SASS FFMA2 = 2 FMAs
#define FMA2(d, a, b)    asm("fma.rn.f32x2 %0, %1, %2, %0;" : "+l"(d) : "l"(a), "l"(b))
#define PACK2(d, lo, hi) asm("mov.b64 %0, {%1, %2};" : "=l"(d) : "f"(lo), "f"(hi))
#define BARN(id, n) asm volatile("bar.sync %0, %1;" :: "r"(id), "n"(n) : "memory")

// Device-global scratch
__device__ float g_U[NCHAR * HID];            // U = embeddings @ W_ih^T
__device__ float g_h[2][BATCH * HID];         // ping-pong hidden state
__device__ unsigned g_pflag[4][32][32];       // [tb][producer tj][pad]: flag, own 128B line
__device__ unsigned g_epoch[GRID];            // per-CTA launch epoch (monotonic tags)

// ---------------------------------------------------------------------------
// Kernel 0: U[c][j] = sum_e emb[c][e] * W_ih[j][e]
// ---------------------------------------------------------------------------
__global__ void u_kernel(const float* __restrict__ emb, const float* __restrict__ wih) {
    int gt   = blockIdx.x * blockDim.x + threadIdx.x;
    int warp = gt >> 5;
    int lane = gt & 31;
    int e0   = lane * 8;
    for (int i = 0; i < 32; i++) {
        int o = warp * 32 + i;
        int c = o >> 10;
        int j = o & 1023;
        const float4* ep = (const float4*)(emb + c * EMB + e0);
        const float4* wp = (const float4*)(wih + j * EMB + e0);
        float4 e1 = __ldg(ep),     e2 = __ldg(ep + 1);
        float4 w1 = __ldg(wp),     w2 = __ldg(wp + 1);
        float acc = e1.x*w1.x + e1.y*w1.y + e1.z*w1.z + e1.w*w1.w
                  + e2.x*w2.x + e2.y*w2.y + e2.z*w2.z + e2.w*w2.w;
        acc += __shfl_xor_sync(0xffffffffu, acc, 16);
        acc += __shfl_xor_sync(0xffffffffu, acc, 8);
        acc += __shfl_xor_sync(0xffffffffu, acc, 4);
        acc += __shfl_xor_sync(0xffffffffu, acc, 2);
        acc += __shfl_xor_sync(0xffffffffu, acc, 1);
        if (lane == 0) g_U[c * HID + j] = acc;
    }
}

// ---------------------------------------------------------------------------
// Persistent RNN scan — R16 with pair-local staging->GEMM coupling.
// Warp w: bhalf = w&1, kq = w>>1. Pair kq = warps {2kq, 2kq+1}.
// Staging: warp w stages producers 4w..4w+3 (k in [128w, 128w+128)) -> the
// pair stages exactly k in [256kq, 256kq+256), which is what it consumes.
// GEMM k-walk (contiguous): k = 256*kq + 4*kk + ks, kk = 0..63.
// Pre-GEMM sync = named 64-thread pair barrier (id 1+kq), NOT syncthreads.
// ---------------------------------------------------------------------------
__global__ void __launch_bounds__(NTHREADS, 1) rnn_kernel(
    const int*   __restrict__ tids,
    const float* __restrict__ whh,
    const float* __restrict__ h0,
    const float* __restrict__ wproj,
    const float* __restrict__ bproj,
    float*       __restrict__ out)
{
    extern __shared__ float smem[];
    float* sW = smem;                         // [1024][32]   W slice, transposed
    float* sH = smem + SW_FLOATS;             // [1024][20]   h tile (pair-private rows)
    float* sP = smem + SW_FLOATS + SH_FLOATS; // [4][16][34]  cross-warp partials

    const int tid = threadIdx.x;
    const int cta = blockIdx.x;
    const int tb  = cta >> 5;      // 0..3 (flag group)
    const int tj  = cta & 31;      // 0..31
    const int b0  = tb * BT;
    const int j0  = tj * JT;

    // per-launch monotonic tag base (graph replays see strictly larger tags)
    __shared__ unsigned s_tagbase;
    if (tid == 0) {
        unsigned e = g_epoch[cta] + 1u;
        g_epoch[cta] = e;
        s_tagbase = e * 1024u;
    }

    // one-time: W_hh slice transposed into SMEM
    for (int idx = tid; idx < JT * HID; idx += NTHREADS) {
        int jj = idx >> 10;
        int k  = idx & 1023;
        sW[k * JT + jj] = whh[(j0 + jj) * HID + k];
    }
    // one-time: init h ping buffer (this CTA's tile)
    for (int idx = tid; idx < BT * JT; idx += NTHREADS) {
        int bb = idx >> 5;
        int jj = idx & 31;
        g_h[0][(b0 + bb) * HID + (j0 + jj)] = h0[j0 + jj];
    }
    __syncthreads();
    const unsigned tagbase = s_tagbase;
    if (tid == 0) {                 // publish h(0) ready
        __threadfence();
        asm volatile("st.relaxed.gpu.global.u32 [%0], %1;"
                     :: "l"(&g_pflag[tb][tj][0]), "r"(tagbase) : "memory");
    }

    const int w = tid >> 5;
    const int l = tid & 31;

    const int bhalf = w & 1;
    const int kq    = w >> 1;
    const int jg    = l & 7;
    const int ks    = l >> 3;

    // staging lane mapping: lane -> (bb 0..15, ki 0..1); warp w owns slices 4w..4w+3
    const int st_bb = l & 15;
    const int st_ki = l >> 4;
    const int pbase = w * 4;

    // combine mapping (R6/R16)
    const int jc  = tid & 31;
    const int bpg = tid >> 5;
    const int cbh = bpg >> 2;
    const int cbp = bpg & 3;
    const int cg  = cbh * 8 + (jc >> 2);
    const int cbase = cbp * 8 + (jc & 3) * 2;
    const int cb0 = b0 + cbh * 8 + cbp * 2;

    // GEMM pointers: contiguous pair-private k-block
    const float* hptr0 = sH + (256 * kq + ks) * SH_STRIDE + bhalf * 8;
    const float* wptr0 = sW + (256 * kq + ks) * JT + jg * 4;

    for (int s = 0; s < SEQ; s++) {
        const int cur = s & 1;
        const int nxt = cur ^ 1;
        const unsigned tag = tagbase + (unsigned)s;

        // ---- wait for THIS warp's 4 producers (h(s) slices), then stage them ----
        {
            unsigned v = tag;
            const int p = pbase + l;           // lanes 0..3 poll; others satisfied
            do {
                if (l < 4)
                    asm volatile("ld.relaxed.gpu.global.u32 %0, [%1];"
                                 : "=r"(v) : "l"(&g_pflag[tb][p][0]) : "memory");
            } while (!__all_sync(0xffffffffu, (int)(v - tag) >= 0));
            __threadfence();                   // acquire: flag seen -> h loads valid

            #pragma unroll
            for (int i = 0; i < 4; i++) {
                const int k0 = (pbase + i) * 32;
                const float* hrow = g_h[cur] + (b0 + st_bb) * HID + k0 + st_ki * 4;
                float* shb = sH + st_bb;
                #pragma unroll
                for (int m = 0; m < 4; m++) {
                    int k = k0 + st_ki * 4 + m * 8;
                    float4 v4 = __ldcg((const float4*)(hrow + m * 8));
                    shb[(k + 0) * SH_STRIDE] = v4.x;
                    shb[(k + 1) * SH_STRIDE] = v4.y;
                    shb[(k + 2) * SH_STRIDE] = v4.z;
                    shb[(k + 3) * SH_STRIDE] = v4.w;
                }
            }
        }
        // pair-local barrier: partner warp's staging visible; GEMM may start
        // as soon as THIS pair's 8 producers are done (not all 32).
        BARN(1 + kq, 64);

        // ---- packed f32x2 partial GEMM: 8b x 4j per lane, 64 contiguous-walk k's ----
        u64 acc[4][4];
        #pragma unroll
        for (int bp = 0; bp < 4; bp++)
            #pragma unroll
            for (int j = 0; j < 4; j++) acc[bp][j] = 0ull;

        const float* hptr = hptr0;
        const float* wptr = wptr0;
        #pragma unroll 4
        for (int kk = 0; kk < 64; kk++) {
            float4 hA = *(const float4*)hptr;
            float4 hB = *(const float4*)(hptr + 4);
            float4 wv = *(const float4*)wptr;
            hptr += 4 * SH_STRIDE;
            wptr += 4 * JT;

            u64 hp[4], wd[4];
            PACK2(hp[0], hA.x, hA.y);  PACK2(hp[1], hA.z, hA.w);
            PACK2(hp[2], hB.x, hB.y);  PACK2(hp[3], hB.z, hB.w);
            PACK2(wd[0], wv.x, wv.x);  PACK2(wd[1], wv.y, wv.y);
            PACK2(wd[2], wv.z, wv.z);  PACK2(wd[3], wv.w, wv.w);

            #pragma unroll
            for (int bp = 0; bp < 4; bp++)
                #pragma unroll
                for (int j = 0; j < 4; j++)
                    FMA2(acc[bp][j], hp[bp], wd[j]);
        }

        // ---- intra-warp reduce over ks (lane bits 3,4), then stash partials ----
        #pragma unroll
        for (int bp = 0; bp < 4; bp++) {
            #pragma unroll
            for (int j = 0; j < 4; j++) {
                float lo = __uint_as_float((unsigned)(acc[bp][j] & 0xffffffffull));
                float hi = __uint_as_float((unsigned)(acc[bp][j] >> 32));
                lo += __shfl_xor_sync(0xffffffffu, lo, 8);
                hi += __shfl_xor_sync(0xffffffffu, hi, 8);
                lo += __shfl_xor_sync(0xffffffffu, lo, 16);
                hi += __shfl_xor_sync(0xffffffffu, hi, 16);
                if (ks == 0) {
                    int g = bhalf * 8 + jg;
                    *(float2*)(sP + (kq * 16 + g) * SP_STRIDE + bp * 8 + j * 2)
                        = make_float2(lo, hi);
                }
            }
        }
        __syncthreads();            // all pairs' partials visible

        // ---- combine 4 kq partials, add U, tanh, write next h ----
        {
            float slo = 0.f, shi = 0.f;
            #pragma unroll
            for (int q = 0; q < 4; q++) {
                float2 v = *(const float2*)(sP + (q * 16 + cg) * SP_STRIDE + cbase);
                slo += v.x; shi += v.y;
            }
            const int c0 = __ldg(&tids[cb0 * SEQ + s]);
            const int c1 = __ldg(&tids[(cb0 + 1) * SEQ + s]);
            float hn0 = tanhf(slo + __ldg(&g_U[c0 * HID + j0 + jc]));
            float hn1 = tanhf(shi + __ldg(&g_U[c1 * HID + j0 + jc]));
            __stcg(&g_h[nxt][cb0 * HID + j0 + jc], hn0);
            __stcg(&g_h[nxt][(cb0 + 1) * HID + j0 + jc], hn1);
        }
        __syncthreads();            // all h stores issued before flag

        if (tid == 0) {             // publish h(s+1) ready (also read-release)
            __threadfence();
            asm volatile("st.relaxed.gpu.global.u32 [%0], %1;"
                         :: "l"(&g_pflag[tb][tj][0]), "r"(tag + 1u) : "memory");
        }
    }

    // ---- wait for final h (this warp's 4 producers at tag SEQ) ----
    {
        const unsigned tag = tagbase + (unsigned)SEQ;
        unsigned v = tag;
        const int p = pbase + l;
        do {
            if (l < 4)
                asm volatile("ld.relaxed.gpu.global.u32 %0, [%1];"
                             : "=r"(v) : "l"(&g_pflag[tb][p][0]) : "memory");
        } while (!__all_sync(0xffffffffu, (int)(v - tag) >= 0));
        __threadfence();
    }
    __syncthreads();

    // ---- final projection: out[b][c] = h_final[b] . W_proj[c] + b_proj[c] ----
    if (tid < 64) {
        const int bb = tid >> 2;
        const int cc = tid & 3;
        const int b  = b0 + bb;
        const int ch = tj * 4 + cc;
        const float* hp = g_h[0] + b * HID;
        const float* wp = wproj + ch * HID;
        float acc2 = 0.0f;
        #pragma unroll 4
        for (int k = 0; k < HID; k += 4) {
            float4 hv = __ldcg((const float4*)(hp + k));
            float4 wv = *(const float4*)(wp + k);
            acc2 += hv.x*wv.x + hv.y*wv.y + hv.z*wv.z + hv.w*wv.w;
        }
        out[b * NCHAR + ch] = acc2 + bproj[ch];
    }
}

// ---------------------------------------------------------------------------
// Launch: graph-capturable, no allocations, no syncs.
// Inputs: t, embeddings, W_ih, W_hh, h0, W_proj, b_proj.
// ---------------------------------------------------------------------------
extern "C" void kernel_launch(void* const* d_in, const int* in_sizes, int n_in,
                              void* d_out, int out_size)
{
    const int*   t     = (const int*)  d_in[0];
    const float* emb   = (const float*)d_in[1];
    const float* wih   = (const float*)d_in[2];
    const float* whh   = (const float*)d_in[3];
    const float* h0    = (const float*)d_in[4];
    const float* wproj = (const float*)d_in[5];
    const float* bproj = (const float*)d_in[6];
    float*       out   = (float*)d_out;

    cudaFuncSetAttribute(rnn_kernel, cudaFuncAttributeMaxDynamicSharedMemorySize, SMEM_BYTES);

    u_kernel<<<512, 256>>>(emb, wih);
    rnn_kernel<<<GRID, NTHREADS, SMEM_BYTES>>>(t, whh, h0, wproj, bproj, out);
}